// round 8
// baseline (speedup 1.0000x reference)
#include <cuda_runtime.h>
#include <math.h>
#include <stdint.h>

#define POOLK 7
#define HH 50
#define WW 50
#define CC 512
#define NROIS 300
#define NPOS (HH * WW)
#define NBINS (POOLK * POOLK)
#define NWORK (NROIS * NBINS)     // 14700 (roi,bin) tasks
#define GRIDB 888                 // 6 blocks/SM; regs forced <=32 -> 8/SM fit => co-resident
#define NWARPS (GRIDB * 8)        // 7104 warps

// Device-global scratch (no allocations allowed).
__device__ float g_part[2 * NPOS];        // per-position partial maxima (float2 layout)
__device__ float g_pool[NWORK];           // pooled bin maxima
__device__ unsigned long long g_sync;     // monotonic grid-sync ticket (never reset)

__device__ __forceinline__ void grid_sync() {
    __syncthreads();
    if (threadIdx.x == 0) {
        __threadfence();  // publish this block's prior global stores
        unsigned long long old = atomicAdd(&g_sync, 1ULL);
        unsigned long long target = (old / GRIDB + 1ULL) * GRIDB;
        unsigned long long v;
        do {
            asm volatile("ld.acquire.gpu.u64 %0, [%1];"
                         : "=l"(v) : "l"(&g_sync) : "memory");
        } while (v < target);
    }
    __syncthreads();
}

__global__ void __launch_bounds__(256, 8)
fused_kernel(const float* __restrict__ fm, const float* __restrict__ rois,
             float* __restrict__ out) {
    const int tid = threadIdx.x;
    const int wid = tid >> 5;
    const int lane = tid & 31;
    const int gw = blockIdx.x * 8 + wid;   // global warp id, 0..7103

    // ---- Phase A: partial channel maxima, 2 warps per position ------------
    // Warp (pos, half) reduces 256 channels: 2 x float4 per lane.
    {
        const int pos = gw >> 1;
        const int half = gw & 1;
        if (pos < NPOS) {
            const float4* p = reinterpret_cast<const float4*>(fm + (size_t)pos * CC)
                              + half * 64;
            const float4 a = p[lane];
            const float4 b = p[lane + 32];
            float m = fmaxf(fmaxf(fmaxf(a.x, a.y), fmaxf(a.z, a.w)),
                            fmaxf(fmaxf(b.x, b.y), fmaxf(b.z, b.w)));
#pragma unroll
            for (int o = 16; o; o >>= 1)
                m = fmaxf(m, __shfl_xor_sync(0xffffffffu, m, o));
            if (lane == 0) g_part[pos * 2 + half] = m;
        }
    }

    grid_sync();

    // ---- Phase B: one thread per (roi,bin): pooled max -> g_pool ----------
    {
        const int task = blockIdx.x * 256 + tid;  // only first 58 blocks work
        if (task < NWORK) {
            const int roi = task / NBINS;          // const divisors -> mul/shift
            const int bin = task - roi * NBINS;
            const int ph = bin / POOLK;
            const int pw = bin - ph * POOLK;

            const float* r = rois + roi * 5;
            // truncation matches astype(int32) for nonneg; *0.0625f exact (== /16)
            const int x1 = (int)(__ldg(r + 1) * 0.0625f);
            const int y1 = (int)(__ldg(r + 2) * 0.0625f);
            const int x2 = (int)(__ldg(r + 3) * 0.0625f);
            const int y2 = (int)(__ldg(r + 4) * 0.0625f);
            const int rh = y2 - y1 + 1;
            const int rw = x2 - x1 + 1;

            const int hs = min(max(y1 + (ph * rh) / POOLK, 0), HH);
            const int he = min(max(y1 + ((ph + 1) * rh + POOLK - 1) / POOLK, 0), HH);
            const int ws = min(max(x1 + (pw * rw) / POOLK, 0), WW);
            const int we = min(max(x1 + ((pw + 1) * rw + POOLK - 1) / POOLK, 0), WW);

            float m = -INFINITY;
            for (int h = hs; h < he; ++h) {
                const float2* row = reinterpret_cast<const float2*>(g_part) + h * WW;
#pragma unroll 5
                for (int w = ws; w < we; ++w) {
                    const float2 v = __ldg(row + w);
                    m = fmaxf(m, fmaxf(v.x, v.y));
                }
            }
            g_pool[task] = m;
        }
    }

    grid_sync();

    // ---- Phase C: pure broadcast store, warp per bin (grid-strided) -------
    for (int b = gw; b < NWORK; b += NWARPS) {
        const float v = __ldg(g_pool + b);
        float4* o4 = reinterpret_cast<float4*>(out) + (size_t)b * (CC / 4);
        const float4 vv = make_float4(v, v, v, v);
#pragma unroll
        for (int i = 0; i < 4; ++i)
            o4[lane + 32 * i] = vv;
    }
}

extern "C" void kernel_launch(void* const* d_in, const int* in_sizes, int n_in,
                              void* d_out, int out_size) {
    const float* rois = (const float*)d_in[0];
    const float* fm = (const float*)d_in[1];
    if (n_in >= 2 && in_sizes[0] > in_sizes[1]) {
        rois = (const float*)d_in[1];
        fm = (const float*)d_in[0];
    }
    float* out = (float*)d_out;

    fused_kernel<<<GRIDB, 256>>>(fm, rois, out);
}

// round 9
// speedup vs baseline: 1.4367x; 1.4367x over previous
#include <cuda_runtime.h>
#include <math.h>

#define POOLK 7
#define HH 50
#define WW 50
#define CC 512
#define NROIS 300
#define NPOS (HH * WW)

// Device-global scratch (no allocations allowed).
__device__ float g_fmax[NPOS];  // 10 KB channel-max map, L2/L1-resident

// ---------------------------------------------------------------------------
// Kernel 1: fmax[h][w] = max_c feature_maps[h][w][c]
// 128 threads per spatial position (1 float4 each) -> 320K threads, high occ.
// ---------------------------------------------------------------------------
__global__ void __launch_bounds__(256) fmax_kernel(const float* __restrict__ fm) {
    const int gid = blockIdx.x * 256 + threadIdx.x;
    const int pos = gid >> 7;               // grid sized exactly
    const int t = threadIdx.x & 127;
    const int grp = threadIdx.x >> 7;
    const int w4 = (threadIdx.x >> 5) & 3;
    const int lane = threadIdx.x & 31;

    const float4 v = reinterpret_cast<const float4*>(fm + (size_t)pos * CC)[t];
    float m = fmaxf(fmaxf(v.x, v.y), fmaxf(v.z, v.w));
#pragma unroll
    for (int o = 16; o; o >>= 1)
        m = fmaxf(m, __shfl_xor_sync(0xffffffffu, m, o));

    __shared__ float part[2][4];
    if (lane == 0) part[grp][w4] = m;
    __syncthreads();
    if (t == 0)
        g_fmax[pos] = fmaxf(fmaxf(part[grp][0], part[grp][1]),
                            fmaxf(part[grp][2], part[grp][3]));
}

// ---------------------------------------------------------------------------
// Kernel 2: one block per (roi, ph).
//  - Warps 0..6 (only) run the prologue + compute bin pw=wid:
//    static 5x5 lane map (bin span <= 5x5 since rh,rw in [3,26]), ONE
//    predicated load from g_fmax, 5 shfl -> sbin[wid]. No division, no loop.
//  - After the barrier all 8 warps do a fully-unrolled broadcast store:
//    896 float4 = 3 full slots + 1 half slot, 4 pre-loaded LDS values.
// ---------------------------------------------------------------------------
__global__ void __launch_bounds__(256) roi_kernel(const float* __restrict__ rois,
                                                  float* __restrict__ out) {
    __shared__ float sbin[8];              // [7] never written, never stored

    const int tid = threadIdx.x;
    const int wid = tid >> 5;
    const int lane = tid & 31;

    if (wid < POOLK) {
        const int roi = blockIdx.x / POOLK;
        const int ph = blockIdx.x - roi * POOLK;
        const int pw = wid;

        const float* r = rois + roi * 5;
        // truncation matches astype(int32) for nonneg; *0.0625f exact (== /16)
        const int x1 = (int)(__ldg(r + 1) * 0.0625f);
        const int y1 = (int)(__ldg(r + 2) * 0.0625f);
        const int x2 = (int)(__ldg(r + 3) * 0.0625f);
        const int y2 = (int)(__ldg(r + 4) * 0.0625f);
        const int rh = y2 - y1 + 1;
        const int rw = x2 - x1 + 1;

        const int hs = min(max(y1 + (ph * rh) / POOLK, 0), HH);
        const int he = min(max(y1 + ((ph + 1) * rh + POOLK - 1) / POOLK, 0), HH);
        const int ws = min(max(x1 + (pw * rw) / POOLK, 0), WW);
        const int we = min(max(x1 + ((pw + 1) * rw + POOLK - 1) / POOLK, 0), WW);
        const int nh = he - hs;
        const int nw = we - ws;

        const int dh = lane / 5;           // const divisors -> mul/shift
        const int dw = lane - dh * 5;

        float m = -INFINITY;
        if (dh < nh && dw < nw)
            m = __ldg(g_fmax + (hs + dh) * WW + (ws + dw));
#pragma unroll
        for (int o = 16; o; o >>= 1)
            m = fmaxf(m, __shfl_xor_sync(0xffffffffu, m, o));
        if (lane == 0) sbin[pw] = m;
    }
    __syncthreads();

    // Store 7*512 floats = 896 float4. Thread t covers idx = t, t+256, t+512,
    // (t+768 if t<128); bin(idx) = idx>>7 = b0 + 2i with b0 = t>>7.
    const int b0 = tid >> 7;
    const float v0 = sbin[b0];
    const float v1 = sbin[b0 + 2];
    const float v2 = sbin[b0 + 4];
    const float v3 = sbin[b0 + 6];        // garbage when b0==1; store predicated off

    float4* o4 = reinterpret_cast<float4*>(out) + (size_t)blockIdx.x * (POOLK * CC / 4);
    o4[tid]       = make_float4(v0, v0, v0, v0);
    o4[tid + 256] = make_float4(v1, v1, v1, v1);
    o4[tid + 512] = make_float4(v2, v2, v2, v2);
    if (b0 == 0)
        o4[tid + 768] = make_float4(v3, v3, v3, v3);
}

extern "C" void kernel_launch(void* const* d_in, const int* in_sizes, int n_in,
                              void* d_out, int out_size) {
    const float* rois = (const float*)d_in[0];
    const float* fm = (const float*)d_in[1];
    if (n_in >= 2 && in_sizes[0] > in_sizes[1]) {
        rois = (const float*)d_in[1];
        fm = (const float*)d_in[0];
    }
    float* out = (float*)d_out;

    fmax_kernel<<<(NPOS * 128) / 256, 256>>>(fm);      // 1250 blocks
    roi_kernel<<<NROIS * POOLK, 256>>>(rois, out);     // 2100 blocks
}

// round 11
// speedup vs baseline: 1.9286x; 1.3424x over previous
#include <cuda_runtime.h>
#include <math.h>

#define POOLK 7
#define HH 50
#define WW 50
#define CC 512
#define NROIS 300
#define NPOS (HH * WW)

// Device-global scratch (no allocations allowed).
__device__ float g_fmax[NPOS];  // 10 KB channel-max map, L2-resident

// ---------------------------------------------------------------------------
// Kernel 1: fmax[h][w] = max_c feature_maps[h][w][c]
// 128 threads per spatial position (1 float4 each) -> 320K threads, high occ.
// (Byte-identical to the proven R4 kernel.)
// ---------------------------------------------------------------------------
__global__ void __launch_bounds__(256) fmax_kernel(const float* __restrict__ fm) {
    const int gid = blockIdx.x * 256 + threadIdx.x;
    const int pos = gid >> 7;               // grid sized exactly
    const int t = threadIdx.x & 127;
    const int grp = threadIdx.x >> 7;
    const int w4 = (threadIdx.x >> 5) & 3;
    const int lane = threadIdx.x & 31;

    const float4 v = reinterpret_cast<const float4*>(fm + (size_t)pos * CC)[t];
    float m = fmaxf(fmaxf(v.x, v.y), fmaxf(v.z, v.w));
#pragma unroll
    for (int o = 16; o; o >>= 1)
        m = fmaxf(m, __shfl_xor_sync(0xffffffffu, m, o));

    __shared__ float part[2][4];
    if (lane == 0) part[grp][w4] = m;
    __syncthreads();
    if (t == 0)
        g_fmax[pos] = fmaxf(fmaxf(part[grp][0], part[grp][1]),
                            fmaxf(part[grp][2], part[grp][3]));
}

// ---------------------------------------------------------------------------
// Kernel 2: one block per (roi, ph) — the proven R4 structure, with ONE
// addition: cudaGridDependencySynchronize() right before the g_fmax gather.
// Under PDL this kernel launches while fmax_kernel is still running; the ROI
// load + integer box math overlap with fmax's tail, and the wait releases as
// soon as fmax's grid completes (implicit trigger => full visibility).
// ---------------------------------------------------------------------------
__global__ void __launch_bounds__(256) roi_kernel(const float* __restrict__ rois,
                                                  float* __restrict__ out) {
    __shared__ float sbin[POOLK];

    const int roi = blockIdx.x / POOLK;
    const int ph = blockIdx.x - roi * POOLK;

    const float* r = rois + roi * 5;
    // truncation matches astype(int32) for nonneg; *0.0625f exact (== /16)
    const int x1 = (int)(r[1] * 0.0625f);
    const int y1 = (int)(r[2] * 0.0625f);
    const int x2 = (int)(r[3] * 0.0625f);
    const int y2 = (int)(r[4] * 0.0625f);
    const int rh = y2 - y1 + 1;
    const int rw = x2 - x1 + 1;

    const int hs = min(max(y1 + (ph * rh) / POOLK, 0), HH);
    const int he = min(max(y1 + ((ph + 1) * rh + POOLK - 1) / POOLK, 0), HH);

    const int wid = threadIdx.x >> 5;
    const int lane = threadIdx.x & 31;

    // Wait for fmax_kernel's completion (PDL). Everything above ran under it.
    cudaGridDependencySynchronize();

    if (wid < POOLK) {
        const int pw = wid;
        const int ws = min(max(x1 + (pw * rw) / POOLK, 0), WW);
        const int we = min(max(x1 + ((pw + 1) * rw + POOLK - 1) / POOLK, 0), WW);
        const int nh = he - hs;
        const int nw = we - ws;
        const int cnt = (nh > 0 && nw > 0) ? nh * nw : 0;
        float m = -INFINITY;
        for (int e = lane; e < cnt; e += 32) {
            const int dh = e / nw;
            const int dw = e - dh * nw;
            m = fmaxf(m, __ldg(g_fmax + (hs + dh) * WW + (ws + dw)));
        }
#pragma unroll
        for (int o = 16; o; o >>= 1)
            m = fmaxf(m, __shfl_xor_sync(0xffffffffu, m, o));
        if (lane == 0) sbin[pw] = m;
    }
    __syncthreads();

    // Write 7 bins * 512 ch = 896 float4, coalesced. v uniform per 128 threads.
    float4* o = reinterpret_cast<float4*>(out) + (size_t)blockIdx.x * POOLK * (CC / 4);
    const int n4 = POOLK * (CC / 4);  // 896
    for (int idx = threadIdx.x; idx < n4; idx += 256) {
        const float v = sbin[idx >> 7];
        o[idx] = make_float4(v, v, v, v);
    }
}

extern "C" void kernel_launch(void* const* d_in, const int* in_sizes, int n_in,
                              void* d_out, int out_size) {
    const float* rois = (const float*)d_in[0];
    const float* fm = (const float*)d_in[1];
    if (n_in >= 2 && in_sizes[0] > in_sizes[1]) {
        rois = (const float*)d_in[1];
        fm = (const float*)d_in[0];
    }
    float* out = (float*)d_out;

    // Kernel 1: normal launch.
    fmax_kernel<<<(NPOS * 128) / 256, 256>>>(fm);      // 1250 blocks

    // Kernel 2: PDL launch — may start while kernel 1 drains; the in-kernel
    // cudaGridDependencySynchronize() enforces the data dependency.
    cudaLaunchConfig_t cfg = {};
    cfg.gridDim = dim3(NROIS * POOLK, 1, 1);           // 2100 blocks
    cfg.blockDim = dim3(256, 1, 1);
    cfg.dynamicSmemBytes = 0;
    cfg.stream = 0;
    cudaLaunchAttribute attr[1];
    attr[0].id = cudaLaunchAttributeProgrammaticStreamSerialization;
    attr[0].val.programmaticStreamSerializationAllowed = 1;
    cfg.attrs = attr;
    cfg.numAttrs = 1;
    cudaLaunchKernelEx(&cfg, roi_kernel, rois, out);
}